// round 7
// baseline (speedup 1.0000x reference)
#include <cuda_runtime.h>
#include <cstdint>

#define N_ROWS 16384
#define K_CB   8192
#define TPK    10

#define TR   128                 // rows per CTA
#define CC   64                  // codes per chunk
#define NCH  (K_CB / CC)         // 128
#define BLK  256                 // 8 warps = 4 row-warps x 2 col-warps
#define GRID (N_ROWS / TR)       // 128 CTAs -> 1 wave

#define OFF_LOSS 1048576
#define OFF_IDX  1048577
#define OFF_MIND (OFF_IDX + N_ROWS)
#define OFF_PERP (OFF_MIND + N_ROWS)

typedef unsigned long long u64;

// dynamic smem byte offsets
#define SM_XP   0                         // u64[32][128]      32768
#define SM_EP   32768                     // u64[2][32][64]    32768
#define SM_TK   65536                     // u64[2][128][10]   20480
#define SM_ESQ  86016                     // f32[2][64]          512
#define SM_TMX  86528                     // f32[2][128]        1024
#define SM_XSQ  87552                     // f32[128]            512
#define SMEM_BYTES 88064

#define SENT 0xFF800000FFFFFFFFull        // (+inf, idx=~0)

__device__ u64   g_cb2[32 * K_CB];        // paired (-2e): [dp][code]
__device__ float g_esq[K_CB];
__device__ int   g_counts[K_CB];

__device__ __forceinline__ unsigned f2ord(float f) {
    unsigned u = __float_as_uint(f);
    return (u & 0x80000000u) ? ~u : (u | 0x80000000u);
}
__device__ __forceinline__ float ord2f(unsigned o) {
    return __uint_as_float((o & 0x80000000u) ? (o & 0x7fffffffu) : ~o);
}
__device__ __forceinline__ void ffma2(u64& d, u64 a, u64 b) {
    asm("fma.rn.f32x2 %0, %1, %2, %0;" : "+l"(d) : "l"(a), "l"(b));
}
__device__ __forceinline__ float2 upk(u64 v) {
    float2 f; asm("mov.b64 {%0,%1}, %2;" : "=f"(f.x), "=f"(f.y) : "l"(v)); return f;
}
__device__ __forceinline__ void cpasync16(void* smem_dst, const void* gsrc) {
    unsigned saddr = (unsigned)__cvta_generic_to_shared(smem_dst);
    asm volatile("cp.async.cg.shared.global [%0], [%1], 16;" :: "r"(saddr), "l"(gsrc));
}

// ---------------------------------------------------------------------------
// Prep: paired -2-scaled transposed codebook + ||e||^2 + zero counts
// ---------------------------------------------------------------------------
__global__ void __launch_bounds__(256) vq_prep(const float* __restrict__ cb) {
    __shared__ float sh[64][65];
    const int blk = blockIdx.x;            // 128 blocks x 64 codes
    const int t = threadIdx.x;
    const float* src = cb + (size_t)blk * 64 * 64;
#pragma unroll
    for (int k = 0; k < 16; k++) {
        int idx = t + k * 256;
        sh[idx >> 6][idx & 63] = src[idx];
    }
    __syncthreads();
#pragma unroll
    for (int k = 0; k < 8; k++) {
        int o = k * 256 + t;
        int c = o & 63, dp = o >> 6;
        float f0 = -2.0f * sh[c][2 * dp];
        float f1 = -2.0f * sh[c][2 * dp + 1];
        u64 v = ((u64)__float_as_uint(f1) << 32) | (u64)__float_as_uint(f0);
        g_cb2[dp * K_CB + blk * 64 + c] = v;
    }
    if (t < 64) {
        float s = 0.f;
#pragma unroll
        for (int d = 0; d < 64; d++) { float x = sh[t][d]; s = fmaf(x, x, s); }
        g_esq[blk * 64 + t] = s;
        g_counts[blk * 64 + t] = 0;
    }
}

// no-op spacer so ncu's "-s 5 -c 1" lands on vq_main
__global__ void vq_nop() {}

// ---------------------------------------------------------------------------
// Main
// ---------------------------------------------------------------------------
__global__ void __launch_bounds__(BLK) vq_main(
    const float* __restrict__ inp, const float* __restrict__ cb,
    const float* __restrict__ gum, float* __restrict__ out)
{
    extern __shared__ char smraw[];
    u64*   XP  = (u64*)(smraw + SM_XP);
    u64*   EP  = (u64*)(smraw + SM_EP);
    u64*   TK  = (u64*)(smraw + SM_TK);
    float* ESQ = (float*)(smraw + SM_ESQ);
    float* TMX = (float*)(smraw + SM_TMX);
    float* XSQ = (float*)(smraw + SM_XSQ);

    const int t = threadIdx.x, lane = t & 31, wid = t >> 5;
    const int rg = lane >> 3, cg = lane & 7;      // 4 row-groups x 8 code-groups
    const int wrow = wid & 3, wcol = wid >> 2;    // 4 row-warps x 2 col-warps
    const int rowBase = blockIdx.x * TR;

    // ---- stage XP[dp][row] ----
    const u64* xin64 = (const u64*)(inp + (size_t)rowBase * 64);
#pragma unroll
    for (int k = 0; k < 16; k++) {
        int o = k * 256 + t;
        int row = o & 127, dp = o >> 7;
        XP[dp * 128 + row] = xin64[row * 32 + dp];
    }
#pragma unroll
    for (int k = 0; k < 10; k++) TK[k * 256 + t] = SENT;
    TMX[t] = __int_as_float(0x7f800000);          // both lists (2*128)
    __syncthreads();

    if (t < 128) {                                // ||x||^2
        float s = 0.f;
#pragma unroll
        for (int dp = 0; dp < 32; dp++) {
            float2 v = *(const float2*)(XP + dp * 128 + t);
            s = fmaf(v.x, v.x, fmaf(v.y, v.y, s));
        }
        XSQ[t] = s;
    }

    // prologue prefetch chunk 0 (8 KB codes -> 1024 granules? 16KB? = 1024*16B)
#pragma unroll
    for (int k = 0; k < 4; k++) {
        int o = k * 256 + t; int dp = o >> 5, g = o & 31;
        cpasync16(EP + dp * 64 + g * 2, g_cb2 + dp * K_CB + g * 2);
    }
    if (t < 16) cpasync16(ESQ + t * 4, g_esq + t * 4);
    asm volatile("cp.async.commit_group;");

    const u64* xbase = XP + wrow * 32 + rg * 8;
    u64* tkw    = TK + wcol * 1280;
    float* tmxw = TMX + wcol * 128;

    for (int ch = 0; ch < NCH; ++ch) {
        __syncthreads();                          // other buffer free for rewrite
        if (ch + 1 < NCH) {
            int nb = (ch + 1) & 1;
            const u64* src = g_cb2 + (ch + 1) * CC;
#pragma unroll
            for (int k = 0; k < 4; k++) {
                int o = k * 256 + t; int dp = o >> 5, g = o & 31;
                cpasync16(EP + nb * 2048 + dp * 64 + g * 2, src + dp * K_CB + g * 2);
            }
            if (t < 16) cpasync16(ESQ + nb * 64 + t * 4, g_esq + (ch + 1) * CC + t * 4);
            asm volatile("cp.async.commit_group;");
            asm volatile("cp.async.wait_group 1;");
        } else {
            asm volatile("cp.async.wait_group 0;");
        }
        __syncthreads();                          // current chunk visible

        const int buf = ch & 1;
        const u64* ebase = EP + buf * 2048 + wcol * 32 + cg * 4;

        u64 acc[32];
#pragma unroll
        for (int i = 0; i < 32; i++) acc[i] = 0ull;

#pragma unroll 2
        for (int dp = 0; dp < 32; ++dp) {
            const u64* xr = xbase + dp * 128;
            const u64* er = ebase + dp * 64;
            ulonglong2 xa0 = *(const ulonglong2*)(xr + 0);
            ulonglong2 xa1 = *(const ulonglong2*)(xr + 2);
            ulonglong2 xa2 = *(const ulonglong2*)(xr + 4);
            ulonglong2 xa3 = *(const ulonglong2*)(xr + 6);
            ulonglong2 eb0 = *(const ulonglong2*)(er + 0);
            ulonglong2 eb1 = *(const ulonglong2*)(er + 2);
            u64 a[8] = {xa0.x, xa0.y, xa1.x, xa1.y, xa2.x, xa2.y, xa3.x, xa3.y};
            u64 b[4] = {eb0.x, eb0.y, eb1.x, eb1.y};
#pragma unroll
            for (int i = 0; i < 8; i++)
#pragma unroll
                for (int j = 0; j < 4; j++) ffma2(acc[i * 4 + j], a[i], b[j]);
        }

        // ---- distances + gate + rare exact inserts (warp-private lists) ----
        float e2[4];
        {
            float4 q = *(const float4*)(ESQ + buf * 64 + wcol * 32 + cg * 4);
            e2[0] = q.x; e2[1] = q.y; e2[2] = q.z; e2[3] = q.w;
        }
        float sv[32];
#pragma unroll
        for (int i = 0; i < 8; i++)
#pragma unroll
            for (int j = 0; j < 4; j++) {
                float2 p = upk(acc[i * 4 + j]);
                sv[i * 4 + j] = p.x + p.y + e2[j];
            }

        const unsigned cb0 = (unsigned)(ch * CC + wcol * 32 + cg * 4);

#pragma unroll
        for (int i = 0; i < 8; i++) {
            const int row = wrow * 32 + rg * 8 + i;
            const float* s = sv + i * 4;
            float m = fminf(fminf(s[0], s[1]), fminf(s[2], s[3]));
            unsigned bal = __ballot_sync(0xffffffffu, m < tmxw[row]);
            unsigned grp = (bal >> (rg * 8)) & 0xffu;
            while (__any_sync(0xffffffffu, grp != 0)) {
                int src = __ffs(grp) - 1;
                bool mine = (grp != 0) && (cg == src);
                if (grp) grp &= grp - 1;
                if (mine) {
                    u64* Lp = tkw + row * 10;
                    u64 L[TPK];
#pragma unroll
                    for (int k = 0; k < TPK; k++) L[k] = Lp[k];
#pragma unroll
                    for (int c = 0; c < 4; c++) {
                        u64 key = ((u64)f2ord(s[c]) << 32) | (u64)(cb0 + c);
                        if (key < L[TPK - 1]) {
#pragma unroll
                            for (int k = TPK - 1; k >= 1; --k) {
                                bool sh = key < L[k - 1];
                                u64 keep = (key < L[k]) ? key : L[k];
                                L[k] = sh ? L[k - 1] : keep;
                            }
                            if (key < L[0]) L[0] = key;
                        }
                    }
#pragma unroll
                    for (int k = 0; k < TPK; k++) Lp[k] = L[k];
                    tmxw[row] = ord2f((unsigned)(L[TPK - 1] >> 32));
                }
                __syncwarp();
            }
        }
    }

    // ---- epilogue: merge two 10-lists, Gumbel-max, gather ----
    __syncthreads();
    const u64* TK0 = TK;
    const u64* TK1 = TK + 1280;
#pragma unroll 1
    for (int rr = 0; rr < 16; ++rr) {
        const int row = wid * 16 + rr;
        const int rgl = rowBase + row;
        u64 key = 0xFFFFFFFFFFFFFFFFull;
        int rank = 127;
        if (lane < 10)      key = TK0[row * 10 + lane];
        else if (lane < 20) key = TK1[row * 10 + lane - 10];
        if (lane < 20) {
            const u64* oth = (lane < 10) ? (TK1 + row * 10) : (TK0 + row * 10);
            int cnt = 0;
#pragma unroll
            for (int k = 0; k < TPK; k++) cnt += (oth[k] < key);
            rank = ((lane < 10) ? lane : lane - 10) + cnt;
        }
        float dval = ord2f((unsigned)(key >> 32));
        int   idxv = (int)(key & 0xffffffffu);
        float sc = __int_as_float(0xff800000);          // -inf
        if (rank < TPK) sc = gum[(size_t)rgl * TPK + rank] - dval;

        float bsc = sc; int brank = rank; float bd = dval; int bidx = idxv;
#pragma unroll
        for (int off = 16; off; off >>= 1) {
            float osc = __shfl_xor_sync(~0u, bsc, off);
            int   ork = __shfl_xor_sync(~0u, brank, off);
            float od  = __shfl_xor_sync(~0u, bd, off);
            int   oi  = __shfl_xor_sync(~0u, bidx, off);
            bool take = (osc > bsc) || (osc == bsc && ork < brank);
            if (take) { bsc = osc; brank = ork; bd = od; bidx = oi; }
        }
        bool valid = XSQ[row] > 1e-12f;
        int   oidx = valid ? bidx : 0;
        float om   = valid ? (bd + XSQ[row]) : 0.f;
        if (lane == 0) {
            out[OFF_IDX + rgl]  = (float)oidx;
            out[OFF_MIND + rgl] = om;
            if (valid) atomicAdd(&g_counts[oidx], 1);
        }
        if (lane < 16) {
            float4 q = make_float4(0.f, 0.f, 0.f, 0.f);
            if (valid) q = *(const float4*)(cb + (size_t)oidx * 64 + lane * 4);
            *(float4*)(out + (size_t)rgl * 64 + lane * 4) = q;
        }
    }
}

// ---------------------------------------------------------------------------
// Finalize: loss + perplexity
// ---------------------------------------------------------------------------
__global__ void __launch_bounds__(256) vq_finalize(float* __restrict__ out) {
    __shared__ float red[256];
    __shared__ float sh_sum, sh_nv;
    const int t = threadIdx.x;

    float s = 0.f;
    for (int i = t; i < N_ROWS; i += 256) s += out[OFF_MIND + i];
    red[t] = s; __syncthreads();
    for (int o = 128; o; o >>= 1) { if (t < o) red[t] += red[t + o]; __syncthreads(); }
    if (t == 0) sh_sum = red[0];
    __syncthreads();

    float nv = 0.f;
    for (int i = t; i < K_CB; i += 256) nv += (float)g_counts[i];
    red[t] = nv; __syncthreads();
    for (int o = 128; o; o >>= 1) { if (t < o) red[t] += red[t + o]; __syncthreads(); }
    if (t == 0) sh_nv = fmaxf(red[0], 1.0f);
    __syncthreads();

    float nvf = sh_nv;
    float ent = 0.f;
    for (int i = t; i < K_CB; i += 256) {
        float p = (float)g_counts[i] / nvf;
        ent += p * logf(p + 1e-10f);
    }
    red[t] = ent; __syncthreads();
    for (int o = 128; o; o >>= 1) { if (t < o) red[t] += red[t + o]; __syncthreads(); }

    if (t == 0) {
        float loss_vq = sh_sum / (nvf * 64.0f);
        float perp = expf(-red[0]);
        float ploss = -logf(perp + 1e-10f);
        out[OFF_LOSS] = loss_vq + 0.01f * ploss;
        out[OFF_PERP] = perp;
    }
}

// ---------------------------------------------------------------------------
extern "C" void kernel_launch(void* const* d_in, const int* in_sizes, int n_in,
                              void* d_out, int out_size) {
    const float* inp = (const float*)d_in[0];
    const float* cb  = (const float*)d_in[1];
    const float* gum = (const float*)d_in[2];
    float* out = (float*)d_out;

    cudaFuncSetAttribute(vq_main, cudaFuncAttributeMaxDynamicSharedMemorySize, SMEM_BYTES);

    vq_prep<<<K_CB / 64, 256>>>(cb);
    // spacers: make vq_main the 6th launch so ncu (-s 5 -c 1) profiles it
    vq_nop<<<1, 32>>>();
    vq_nop<<<1, 32>>>();
    vq_nop<<<1, 32>>>();
    vq_nop<<<1, 32>>>();
    vq_main<<<GRID, BLK, SMEM_BYTES>>>(inp, cb, gum, out);
    vq_finalize<<<1, 256>>>(out);
}

// round 8
// speedup vs baseline: 1.6808x; 1.6808x over previous
#include <cuda_runtime.h>
#include <cstdint>

#define N_ROWS 16384
#define K_CB   8192
#define D_DIM  64
#define TPK    10

#define TR   128                 // rows per CTA
#define CC   128                 // codes per chunk
#define NCH  (K_CB / CC)         // 64
#define BLK  256                 // 8 warps, 16 rows/warp
#define GRID (N_ROWS / TR)       // 128 CTAs -> exactly 1 wave

#define OFF_LOSS 1048576
#define OFF_IDX  1048577
#define OFF_MIND (OFF_IDX + N_ROWS)
#define OFF_PERP (OFF_MIND + N_ROWS)

// shared layout (float offsets)
#define XD_STR  260                       // padded stride for duplicated x rows
#define SM_XD   0                         // [64][260] : dup'd transposed x
#define SM_ET   (64 * XD_STR)             // 16640 : [2][64][128] code chunks (-2e)
#define SM_TK   (SM_ET + 2 * 64 * 128)    // 33024 : u64 [128][10]
#define SM_XSQ  (SM_TK + TR * TPK * 2)    // 35584
#define SM_TMX  (SM_XSQ + TR)             // 35712
#define SM_FLOATS (SM_TMX + TR)           // 35840
#define SMEM_BYTES (SM_FLOATS * 4)        // 143360

#define SENT 0xFF800000FFFFFFFFull        // key(+inf, idx 0xffffffff)

__device__ float g_cbT[D_DIM * K_CB];     // transposed, scaled: -2*e  [d][code]
__device__ float g_esq[K_CB];
__device__ int   g_counts[K_CB];

__device__ __forceinline__ unsigned f2ord(float f) {
    unsigned u = __float_as_uint(f);
    return (u & 0x80000000u) ? ~u : (u | 0x80000000u);
}
__device__ __forceinline__ float ord2f(unsigned o) {
    return __uint_as_float((o & 0x80000000u) ? (o & 0x7fffffffu) : ~o);
}
__device__ __forceinline__ void ffma2(unsigned long long& d,
                                      unsigned long long a, unsigned long long b) {
    asm("fma.rn.f32x2 %0, %1, %2, %0;" : "+l"(d) : "l"(a), "l"(b));
}
__device__ __forceinline__ float2 upk(unsigned long long v) {
    float2 f; asm("mov.b64 {%0,%1}, %2;" : "=f"(f.x), "=f"(f.y) : "l"(v)); return f;
}
__device__ __forceinline__ void cpasync16(float* smem_dst, const float* gsrc) {
    unsigned saddr = (unsigned)__cvta_generic_to_shared(smem_dst);
    asm volatile("cp.async.cg.shared.global [%0], [%1], 16;" :: "r"(saddr), "l"(gsrc));
}

// ---------------------------------------------------------------------------
// Prep: transposed, -2-scaled codebook + ||e||^2 + zero counts
// ---------------------------------------------------------------------------
__global__ void __launch_bounds__(256) vq_prep(const float* __restrict__ cb) {
    __shared__ float sh[64][65];
    const int blk = blockIdx.x;        // 128 blocks x 64 codes
    const int t = threadIdx.x;
    const float* src = cb + (size_t)blk * 64 * 64;
#pragma unroll
    for (int k = 0; k < 16; k++) {
        int idx = t + k * 256;
        sh[idx >> 6][idx & 63] = src[idx];
    }
    __syncthreads();
#pragma unroll
    for (int k = 0; k < 16; k++) {
        int idx = t + k * 256;
        int d = idx >> 6, c = idx & 63;
        g_cbT[d * K_CB + blk * 64 + c] = -2.0f * sh[c][d];
    }
    if (t < 64) {
        float s = 0.f;
#pragma unroll
        for (int d = 0; d < 64; d++) { float x = sh[t][d]; s = fmaf(x, x, s); }
        g_esq[blk * 64 + t] = s;
        g_counts[blk * 64 + t] = 0;
    }
}

// spacer kernels so the ncu capture window (4th launch) lands on vq_main
__global__ void vq_nop() {}

// ---------------------------------------------------------------------------
// Main
// ---------------------------------------------------------------------------
__global__ void __launch_bounds__(BLK) vq_main(
    const float* __restrict__ inp, const float* __restrict__ cb,
    const float* __restrict__ gum, float* __restrict__ out)
{
    extern __shared__ float sm[];
    float* XD  = sm + SM_XD;
    float* ET  = sm + SM_ET;
    unsigned long long* TK = (unsigned long long*)(sm + SM_TK);
    float* XSQ = sm + SM_XSQ;
    float* TMX = sm + SM_TMX;

    const int t = threadIdx.x, lane = t & 31, wid = t >> 5;
    const int rowBase = blockIdx.x * TR;
    const int rbase = wid * 16;              // 16 rows per warp

    // ---- stage x tile, duplicated+transposed: XD[d][2r],XD[d][2r+1] = x[r][d]
    const float* xin = inp + (size_t)rowBase * 64;
#pragma unroll
    for (int k = 0; k < 32; k++) {
        int o = k * 256 + t;
        int d = o & 63, r = o >> 6;
        float v = xin[o];
        XD[d * XD_STR + 2 * r]     = v;
        XD[d * XD_STR + 2 * r + 1] = v;
    }
    for (int i = t; i < TR * TPK; i += BLK) TK[i] = SENT;
    if (t < TR) TMX[t] = __int_as_float(0x7f800000);

    // prologue: chunk 0 -> buffer 0  (32KB, 8 granules/thread)
#pragma unroll
    for (int k = 0; k < 8; k++) {
        int o = k * 256 + t; int d = o >> 5, seg = o & 31;
        cpasync16(ET + d * 128 + seg * 4, g_cbT + d * K_CB + seg * 4);
    }
    asm volatile("cp.async.commit_group;");
    __syncthreads();

    if (t < TR) {       // ||x||^2 per row (after staging barrier)
        float s = 0.f;
#pragma unroll
        for (int d = 0; d < 64; d++) {
            float x = XD[d * XD_STR + 2 * t];
            s = fmaf(x, x, s);
        }
        XSQ[t] = s;
    }

    for (int ch = 0; ch < NCH; ++ch) {
        float* eb = ET + (ch & 1) * 8192;
        if (ch + 1 < NCH) {
            int nb = (ch + 1) & 1;
            float* en = ET + nb * 8192;
            const float* gsrc = g_cbT + (ch + 1) * CC;
#pragma unroll
            for (int k = 0; k < 8; k++) {
                int o = k * 256 + t; int d = o >> 5, seg = o & 31;
                cpasync16(en + d * 128 + seg * 4, gsrc + d * K_CB + seg * 4);
            }
            asm volatile("cp.async.commit_group;");
            asm volatile("cp.async.wait_group 1;");
        } else {
            asm volatile("cp.async.wait_group 0;");
        }
        __syncthreads();

        // ---- 16 rows x 4 codes via fma.rn.f32x2 : acc = sum_d (-2 e)*x ----
        unsigned long long acc[32];
#pragma unroll
        for (int i = 0; i < 32; i++) acc[i] = 0ull;

        const char* xp = (const char*)(XD + 2 * rbase);
        const char* bp = (const char*)(eb + (lane << 2));
#pragma unroll 2
        for (int d = 0; d < 64; ++d) {
            const ulonglong2* xa = (const ulonglong2*)(xp + (size_t)d * (XD_STR * 4));
            ulonglong2 bv = *(const ulonglong2*)(bp + (size_t)d * 512);
#pragma unroll
            for (int j = 0; j < 8; j++) {
                ulonglong2 av = xa[j];          // rows 2j (dup), 2j+1 (dup)
                ffma2(acc[4 * j + 0], av.x, bv.x);
                ffma2(acc[4 * j + 1], av.x, bv.y);
                ffma2(acc[4 * j + 2], av.y, bv.x);
                ffma2(acc[4 * j + 3], av.y, bv.y);
            }
        }

        // ---- gate + rare exact insert ----
        const float4 e4 = __ldg((const float4*)(g_esq + ch * CC + (lane << 2)));
        const unsigned cbase = (unsigned)(ch * CC + (lane << 2));

#pragma unroll 1
        for (int r = 0; r < 16; ++r) {
            int j = r >> 1, odd = (r & 1) << 1;
            float2 pA = upk(acc[4 * j + odd]);
            float2 pB = upk(acc[4 * j + odd + 1]);
            float s0 = pA.x + e4.x, s1 = pA.y + e4.y;
            float s2 = pB.x + e4.z, s3 = pB.y + e4.w;
            float m = fminf(fminf(s0, s1), fminf(s2, s3));
            int row = rbase + r;
            unsigned bal = __ballot_sync(~0u, m < TMX[row]);
            while (bal) {
                int src = __ffs(bal) - 1; bal &= bal - 1;
                if (lane == src) {
                    unsigned long long L[TPK];
#pragma unroll
                    for (int i = 0; i < TPK; i++) L[i] = TK[row * TPK + i];
                    float ss[4] = {s0, s1, s2, s3};
#pragma unroll
                    for (int c = 0; c < 4; c++) {
                        unsigned long long key =
                            ((unsigned long long)f2ord(ss[c]) << 32) | (cbase + c);
                        if (key < L[TPK - 1]) {
#pragma unroll
                            for (int i = TPK - 1; i >= 1; --i) {
                                bool sh = key < L[i - 1];
                                unsigned long long keep = (key < L[i]) ? key : L[i];
                                L[i] = sh ? L[i - 1] : keep;
                            }
                            if (key < L[0]) L[0] = key;
                        }
                    }
#pragma unroll
                    for (int i = 0; i < TPK; i++) TK[row * TPK + i] = L[i];
                    TMX[row] = ord2f((unsigned)(L[TPK - 1] >> 32));
                }
                __syncwarp();
            }
        }
        __syncthreads();
    }

    // ---- epilogue: Gumbel-max sample, gather, outputs ----
#pragma unroll 1
    for (int r = 0; r < 16; ++r) {
        int row = rbase + r;
        int rg = rowBase + row;
        unsigned long long kk = (lane < TPK) ? TK[row * TPK + lane] : SENT;
        float dv = ord2f((unsigned)(kk >> 32));
        int   ik = (int)(kk & 0xffffffffu);
        float sc = -__int_as_float(0x7f800000);
        if (lane < TPK) sc = gum[(size_t)rg * TPK + lane] - dv;  // const xsq dropped
        float best = -__int_as_float(0x7f800000);
        int bestk = 0;
#pragma unroll
        for (int k = 0; k < TPK; k++) {
            float s = __shfl_sync(~0u, sc, k);
            if (s > best) { best = s; bestk = k; }     // first-index tie-break
        }
        int   selidx = __shfl_sync(~0u, ik, bestk);
        float seld   = __shfl_sync(~0u, dv, bestk) + XSQ[row];
        bool valid = XSQ[row] > 1e-12f;
        int   oidx = valid ? selidx : 0;
        float om   = valid ? seld : 0.f;
        if (lane == 0) {
            out[OFF_IDX + rg]  = (float)oidx;
            out[OFF_MIND + rg] = om;
            if (valid) atomicAdd(&g_counts[oidx], 1);
        }
        if (lane < 16) {
            float4 q = make_float4(0.f, 0.f, 0.f, 0.f);
            if (valid) q = *(const float4*)(cb + (size_t)oidx * 64 + lane * 4);
            *(float4*)(out + (size_t)rg * 64 + lane * 4) = q;
        }
    }
}

// ---------------------------------------------------------------------------
// Finalize: loss + perplexity
// ---------------------------------------------------------------------------
__global__ void __launch_bounds__(256) vq_finalize(float* __restrict__ out) {
    __shared__ float red[256];
    __shared__ float sh_sum, sh_nv;
    const int t = threadIdx.x;

    float s = 0.f;
    for (int i = t; i < N_ROWS; i += 256) s += out[OFF_MIND + i];
    red[t] = s; __syncthreads();
    for (int o = 128; o; o >>= 1) { if (t < o) red[t] += red[t + o]; __syncthreads(); }
    if (t == 0) sh_sum = red[0];
    __syncthreads();

    float nv = 0.f;
    for (int i = t; i < K_CB; i += 256) nv += (float)g_counts[i];
    red[t] = nv; __syncthreads();
    for (int o = 128; o; o >>= 1) { if (t < o) red[t] += red[t + o]; __syncthreads(); }
    if (t == 0) sh_nv = fmaxf(red[0], 1.0f);
    __syncthreads();

    float nvf = sh_nv;
    float ent = 0.f;
    for (int i = t; i < K_CB; i += 256) {
        float p = (float)g_counts[i] / nvf;
        ent += p * logf(p + 1e-10f);
    }
    red[t] = ent; __syncthreads();
    for (int o = 128; o; o >>= 1) { if (t < o) red[t] += red[t + o]; __syncthreads(); }

    if (t == 0) {
        float loss_vq = sh_sum / (nvf * 64.0f);
        float perp = expf(-red[0]);
        float ploss = -logf(perp + 1e-10f);
        out[OFF_LOSS] = loss_vq + 0.01f * ploss;
        out[OFF_PERP] = perp;
    }
}

// ---------------------------------------------------------------------------
extern "C" void kernel_launch(void* const* d_in, const int* in_sizes, int n_in,
                              void* d_out, int out_size) {
    const float* inp = (const float*)d_in[0];
    const float* cb  = (const float*)d_in[1];
    const float* gum = (const float*)d_in[2];
    float* out = (float*)d_out;

    cudaFuncSetAttribute(vq_main, cudaFuncAttributeMaxDynamicSharedMemorySize, SMEM_BYTES);

    vq_prep<<<K_CB / 64, 256>>>(cb);
    // two spacers: previous captures consistently hit the 4th launch,
    // so prep(1), nop(2), nop(3), main(4) puts vq_main in the capture window
    vq_nop<<<1, 32>>>();
    vq_nop<<<1, 32>>>();
    vq_main<<<GRID, BLK, SMEM_BYTES>>>(inp, cb, gum, out);
    vq_finalize<<<1, 256>>>(out);
}

// round 9
// speedup vs baseline: 1.9893x; 1.1835x over previous
#include <cuda_runtime.h>
#include <cstdint>

#define N_ROWS 16384
#define K_CB   8192
#define D_DIM  64
#define TPK    10

#define TR   128                 // rows per CTA
#define CC   128                 // codes per chunk
#define NCH  (K_CB / CC)         // 64
#define BLK  512                 // 16 warps, 8 rows/warp
#define GRID (N_ROWS / TR)       // 128 CTAs -> exactly 1 wave

#define OFF_LOSS 1048576
#define OFF_IDX  1048577
#define OFF_MIND (OFF_IDX + N_ROWS)
#define OFF_PERP (OFF_MIND + N_ROWS)

// shared layout (float offsets)
#define XD_STR  260                       // padded stride for duplicated x rows
#define SM_XD   0                         // [64][260] : dup'd transposed x
#define SM_ET   (64 * XD_STR)             // 16640 : [2][64][128] code chunks (-2e)
#define SM_TK   (SM_ET + 2 * 64 * 128)    // 33024 : u64 [128][10]
#define SM_XSQ  (SM_TK + TR * TPK * 2)    // 35584
#define SM_TMX  (SM_XSQ + TR)             // 35712
#define SM_FLOATS (SM_TMX + TR)           // 35840
#define SMEM_BYTES (SM_FLOATS * 4)        // 143360

#define SENT 0xFF800000FFFFFFFFull        // key(+inf, idx 0xffffffff)

__device__ float g_cbT[D_DIM * K_CB];     // transposed, scaled: -2*e  [d][code]
__device__ float g_esq[K_CB];
__device__ int   g_counts[K_CB];

__device__ __forceinline__ unsigned f2ord(float f) {
    unsigned u = __float_as_uint(f);
    return (u & 0x80000000u) ? ~u : (u | 0x80000000u);
}
__device__ __forceinline__ float ord2f(unsigned o) {
    return __uint_as_float((o & 0x80000000u) ? (o & 0x7fffffffu) : ~o);
}
__device__ __forceinline__ void ffma2(unsigned long long& d,
                                      unsigned long long a, unsigned long long b) {
    asm("fma.rn.f32x2 %0, %1, %2, %0;" : "+l"(d) : "l"(a), "l"(b));
}
__device__ __forceinline__ float2 upk(unsigned long long v) {
    float2 f; asm("mov.b64 {%0,%1}, %2;" : "=f"(f.x), "=f"(f.y) : "l"(v)); return f;
}
__device__ __forceinline__ void cpasync16(float* smem_dst, const float* gsrc) {
    unsigned saddr = (unsigned)__cvta_generic_to_shared(smem_dst);
    asm volatile("cp.async.cg.shared.global [%0], [%1], 16;" :: "r"(saddr), "l"(gsrc));
}

// ---------------------------------------------------------------------------
// Prep: transposed, -2-scaled codebook + ||e||^2 + zero counts
// ---------------------------------------------------------------------------
__global__ void __launch_bounds__(256) vq_prep(const float* __restrict__ cb) {
    __shared__ float sh[64][65];
    const int blk = blockIdx.x;        // 128 blocks x 64 codes
    const int t = threadIdx.x;
    const float* src = cb + (size_t)blk * 64 * 64;
#pragma unroll
    for (int k = 0; k < 16; k++) {
        int idx = t + k * 256;
        sh[idx >> 6][idx & 63] = src[idx];
    }
    __syncthreads();
#pragma unroll
    for (int k = 0; k < 16; k++) {
        int idx = t + k * 256;
        int d = idx >> 6, c = idx & 63;
        g_cbT[d * K_CB + blk * 64 + c] = -2.0f * sh[c][d];
    }
    if (t < 64) {
        float s = 0.f;
#pragma unroll
        for (int d = 0; d < 64; d++) { float x = sh[t][d]; s = fmaf(x, x, s); }
        g_esq[blk * 64 + t] = s;
        g_counts[blk * 64 + t] = 0;
    }
}

// spacer kernels so the ncu capture window (4th launch) lands on vq_main
__global__ void vq_nop() {}

// ---------------------------------------------------------------------------
// Main
// ---------------------------------------------------------------------------
__global__ void __launch_bounds__(BLK) vq_main(
    const float* __restrict__ inp, const float* __restrict__ cb,
    const float* __restrict__ gum, float* __restrict__ out)
{
    extern __shared__ float sm[];
    float* XD  = sm + SM_XD;
    float* ET  = sm + SM_ET;
    unsigned long long* TK = (unsigned long long*)(sm + SM_TK);
    float* XSQ = sm + SM_XSQ;
    float* TMX = sm + SM_TMX;

    const int t = threadIdx.x, lane = t & 31, wid = t >> 5;
    const int rowBase = blockIdx.x * TR;
    const int rbase = wid * 8;               // 8 rows per warp (16 warps)

    // ---- stage x tile, duplicated+transposed: XD[d][2r],XD[d][2r+1] = x[r][d]
    const float* xin = inp + (size_t)rowBase * 64;
#pragma unroll
    for (int k = 0; k < 16; k++) {
        int o = k * 512 + t;
        int d = o & 63, r = o >> 6;
        float v = xin[o];
        XD[d * XD_STR + 2 * r]     = v;
        XD[d * XD_STR + 2 * r + 1] = v;
    }
    for (int i = t; i < TR * TPK; i += BLK) TK[i] = SENT;
    if (t < TR) TMX[t] = __int_as_float(0x7f800000);

    // prologue: chunk 0 -> buffer 0  (32KB, 4 granules/thread)
#pragma unroll
    for (int k = 0; k < 4; k++) {
        int o = k * 512 + t; int d = o >> 5, seg = o & 31;
        cpasync16(ET + d * 128 + seg * 4, g_cbT + d * K_CB + seg * 4);
    }
    asm volatile("cp.async.commit_group;");
    __syncthreads();

    if (t < TR) {       // ||x||^2 per row (after staging barrier)
        float s = 0.f;
#pragma unroll
        for (int d = 0; d < 64; d++) {
            float x = XD[d * XD_STR + 2 * t];
            s = fmaf(x, x, s);
        }
        XSQ[t] = s;
    }

    for (int ch = 0; ch < NCH; ++ch) {
        float* eb = ET + (ch & 1) * 8192;
        if (ch + 1 < NCH) {
            int nb = (ch + 1) & 1;
            float* en = ET + nb * 8192;
            const float* gsrc = g_cbT + (ch + 1) * CC;
#pragma unroll
            for (int k = 0; k < 4; k++) {
                int o = k * 512 + t; int d = o >> 5, seg = o & 31;
                cpasync16(en + d * 128 + seg * 4, gsrc + d * K_CB + seg * 4);
            }
            asm volatile("cp.async.commit_group;");
            asm volatile("cp.async.wait_group 1;");
        } else {
            asm volatile("cp.async.wait_group 0;");
        }
        __syncthreads();

        // ---- 8 rows x 4 codes via fma.rn.f32x2 : acc = sum_d (-2 e)*x ----
        unsigned long long acc[16];
#pragma unroll
        for (int i = 0; i < 16; i++) acc[i] = 0ull;

        const char* xp = (const char*)(XD + 2 * rbase);
        const char* bp = (const char*)(eb + (lane << 2));
#pragma unroll 4
        for (int d = 0; d < 64; ++d) {
            const ulonglong2* xa = (const ulonglong2*)(xp + (size_t)d * (XD_STR * 4));
            ulonglong2 bv = *(const ulonglong2*)(bp + (size_t)d * 512);
#pragma unroll
            for (int j = 0; j < 4; j++) {
                ulonglong2 av = xa[j];          // rows 2j (dup), 2j+1 (dup)
                ffma2(acc[4 * j + 0], av.x, bv.x);
                ffma2(acc[4 * j + 1], av.x, bv.y);
                ffma2(acc[4 * j + 2], av.y, bv.x);
                ffma2(acc[4 * j + 3], av.y, bv.y);
            }
        }

        // ---- gate + rare exact insert ----
        const float4 e4 = __ldg((const float4*)(g_esq + ch * CC + (lane << 2)));
        const unsigned cbase = (unsigned)(ch * CC + (lane << 2));

#pragma unroll 1
        for (int r = 0; r < 8; ++r) {
            int j = r >> 1, odd = (r & 1) << 1;
            float2 pA = upk(acc[4 * j + odd]);
            float2 pB = upk(acc[4 * j + odd + 1]);
            float s0 = pA.x + e4.x, s1 = pA.y + e4.y;
            float s2 = pB.x + e4.z, s3 = pB.y + e4.w;
            float m = fminf(fminf(s0, s1), fminf(s2, s3));
            int row = rbase + r;
            unsigned bal = __ballot_sync(~0u, m < TMX[row]);
            while (bal) {
                int src = __ffs(bal) - 1; bal &= bal - 1;
                if (lane == src) {
                    unsigned long long L[TPK];
#pragma unroll
                    for (int i = 0; i < TPK; i++) L[i] = TK[row * TPK + i];
                    float ss[4] = {s0, s1, s2, s3};
#pragma unroll
                    for (int c = 0; c < 4; c++) {
                        unsigned long long key =
                            ((unsigned long long)f2ord(ss[c]) << 32) | (cbase + c);
                        if (key < L[TPK - 1]) {
#pragma unroll
                            for (int i = TPK - 1; i >= 1; --i) {
                                bool sh = key < L[i - 1];
                                unsigned long long keep = (key < L[i]) ? key : L[i];
                                L[i] = sh ? L[i - 1] : keep;
                            }
                            if (key < L[0]) L[0] = key;
                        }
                    }
#pragma unroll
                    for (int i = 0; i < TPK; i++) TK[row * TPK + i] = L[i];
                    TMX[row] = ord2f((unsigned)(L[TPK - 1] >> 32));
                }
                __syncwarp();
            }
        }
        __syncthreads();
    }

    // ---- epilogue: Gumbel-max sample, gather, outputs ----
#pragma unroll 1
    for (int r = 0; r < 8; ++r) {
        int row = rbase + r;
        int rg = rowBase + row;
        unsigned long long kk = (lane < TPK) ? TK[row * TPK + lane] : SENT;
        float dv = ord2f((unsigned)(kk >> 32));
        int   ik = (int)(kk & 0xffffffffu);
        float sc = -__int_as_float(0x7f800000);
        if (lane < TPK) sc = gum[(size_t)rg * TPK + lane] - dv;  // const xsq dropped
        float best = -__int_as_float(0x7f800000);
        int bestk = 0;
#pragma unroll
        for (int k = 0; k < TPK; k++) {
            float s = __shfl_sync(~0u, sc, k);
            if (s > best) { best = s; bestk = k; }     // first-index tie-break
        }
        int   selidx = __shfl_sync(~0u, ik, bestk);
        float seld   = __shfl_sync(~0u, dv, bestk) + XSQ[row];
        bool valid = XSQ[row] > 1e-12f;
        int   oidx = valid ? selidx : 0;
        float om   = valid ? seld : 0.f;
        if (lane == 0) {
            out[OFF_IDX + rg]  = (float)oidx;
            out[OFF_MIND + rg] = om;
            if (valid) atomicAdd(&g_counts[oidx], 1);
        }
        if (lane < 16) {
            float4 q = make_float4(0.f, 0.f, 0.f, 0.f);
            if (valid) q = *(const float4*)(cb + (size_t)oidx * 64 + lane * 4);
            *(float4*)(out + (size_t)rg * 64 + lane * 4) = q;
        }
    }
}

// ---------------------------------------------------------------------------
// Finalize: loss + perplexity
// ---------------------------------------------------------------------------
__global__ void __launch_bounds__(256) vq_finalize(float* __restrict__ out) {
    __shared__ float red[256];
    __shared__ float sh_sum, sh_nv;
    const int t = threadIdx.x;

    float s = 0.f;
    for (int i = t; i < N_ROWS; i += 256) s += out[OFF_MIND + i];
    red[t] = s; __syncthreads();
    for (int o = 128; o; o >>= 1) { if (t < o) red[t] += red[t + o]; __syncthreads(); }
    if (t == 0) sh_sum = red[0];
    __syncthreads();

    float nv = 0.f;
    for (int i = t; i < K_CB; i += 256) nv += (float)g_counts[i];
    red[t] = nv; __syncthreads();
    for (int o = 128; o; o >>= 1) { if (t < o) red[t] += red[t + o]; __syncthreads(); }
    if (t == 0) sh_nv = fmaxf(red[0], 1.0f);
    __syncthreads();

    float nvf = sh_nv;
    float ent = 0.f;
    for (int i = t; i < K_CB; i += 256) {
        float p = (float)g_counts[i] / nvf;
        ent += p * logf(p + 1e-10f);
    }
    red[t] = ent; __syncthreads();
    for (int o = 128; o; o >>= 1) { if (t < o) red[t] += red[t + o]; __syncthreads(); }

    if (t == 0) {
        float loss_vq = sh_sum / (nvf * 64.0f);
        float perp = expf(-red[0]);
        float ploss = -logf(perp + 1e-10f);
        out[OFF_LOSS] = loss_vq + 0.01f * ploss;
        out[OFF_PERP] = perp;
    }
}

// ---------------------------------------------------------------------------
extern "C" void kernel_launch(void* const* d_in, const int* in_sizes, int n_in,
                              void* d_out, int out_size) {
    const float* inp = (const float*)d_in[0];
    const float* cb  = (const float*)d_in[1];
    const float* gum = (const float*)d_in[2];
    float* out = (float*)d_out;

    cudaFuncSetAttribute(vq_main, cudaFuncAttributeMaxDynamicSharedMemorySize, SMEM_BYTES);

    vq_prep<<<K_CB / 64, 256>>>(cb);
    // two spacers keep vq_main in the ncu capture window (4th launch)
    vq_nop<<<1, 32>>>();
    vq_nop<<<1, 32>>>();
    vq_main<<<GRID, BLK, SMEM_BYTES>>>(inp, cb, gum, out);
    vq_finalize<<<1, 256>>>(out);
}